// round 10
// baseline (speedup 1.0000x reference)
#include <cuda_runtime.h>
#include <cstdint>

// Problem constants
constexpr int B  = 4;
constexpr int T  = 4096;
constexpr int C  = 512;
constexpr int HS = 64;
// Q pre-scale folded into projection: (1/sqrt(64)) * log2(e)
constexpr float QSCALE = 0.18033688011112042f;

// Scratch — __device__ globals, no allocation.
__device__ __align__(16) float g_q[B * T * HS];   // tf32-rounded, pre-scaled
__device__ __align__(16) float g_k[B * T * HS];   // tf32-rounded
__device__ __align__(16) float g_vt[B * T * HS];  // [b][tile][dim][key], tf32-rounded

// ---------------------------------------------------------------------------
// Helpers (sm_80-level PTX only — safe for compute_100 baseline target)
// ---------------------------------------------------------------------------
__device__ __forceinline__ float cvt_tf32(float x) {
    uint32_t y;                        // tf32 cvt destination must be .b32
    asm("cvt.rna.tf32.f32 %0, %1;" : "=r"(y) : "f"(x));
    return __uint_as_float(y);
}
__device__ __forceinline__ float fast_exp2(float x) {
    float y;
    asm("ex2.approx.f32 %0, %1;" : "=f"(y) : "f"(x));
    return y;
}
__device__ __forceinline__ void cp16(uint32_t dst, const void* src) {
    asm volatile("cp.async.cg.shared.global [%0], [%1], 16;" :: "r"(dst), "l"(src));
}
#define CP_COMMIT() asm volatile("cp.async.commit_group;" ::: "memory")
#define CP_WAIT(n)  asm volatile("cp.async.wait_group %0;" :: "n"(n) : "memory")
// Named barrier: group g (128 threads) syncs on id 1+g.
__device__ __forceinline__ void bar_group(int id) {
    asm volatile("bar.sync %0, 128;" :: "r"(id) : "memory");
}

__device__ __forceinline__ void ldm4(uint32_t& r0, uint32_t& r1, uint32_t& r2,
                                     uint32_t& r3, uint32_t addr) {
    asm volatile("ldmatrix.sync.aligned.m8n8.x4.shared.b16 {%0,%1,%2,%3}, [%4];"
                 : "=r"(r0), "=r"(r1), "=r"(r2), "=r"(r3) : "r"(addr));
}
// D(16x8,f32) += A(16x8,tf32) * B(8x8,tf32)
__device__ __forceinline__ void mma8(float* d, const uint32_t* a, const uint32_t* b) {
    asm volatile(
        "mma.sync.aligned.m16n8k8.row.col.f32.tf32.tf32.f32 "
        "{%0,%1,%2,%3},{%4,%5,%6,%7},{%8,%9},{%0,%1,%2,%3};"
        : "+f"(d[0]), "+f"(d[1]), "+f"(d[2]), "+f"(d[3])
        : "r"(a[0]), "r"(a[1]), "r"(a[2]), "r"(a[3]), "r"(b[0]), "r"(b[1]));
}

// ---------------------------------------------------------------------------
// Fused projection — IDENTICAL to R9 (passing). One pass over x -> q, k, vt.
// ---------------------------------------------------------------------------
__global__ __launch_bounds__(256) void proj_fused(
    const float* __restrict__ x,
    const float* __restrict__ Wk,
    const float* __restrict__ Wq,
    const float* __restrict__ Wv)
{
    __shared__ float xs[64][33];        // 8.4 KB
    __shared__ float ws[3][32][64];     // 24 KB; reused as ts[64*65] in epilogue

    const int tid = threadIdx.x;
    const int tx = tid & 15, ty = tid >> 4;
    const int row0 = blockIdx.x * 64;

    const float* Wm[3] = {Wq, Wk, Wv};

    float acc[3][4][4] = {};

    for (int k0 = 0; k0 < C; k0 += 32) {
        __syncthreads();
        #pragma unroll
        for (int t = 0; t < 2; t++) {
            int f = tid * 2 + t;
            int r = f >> 3;
            int c = (f & 7) * 4;
            float4 v4 = *reinterpret_cast<const float4*>(
                x + (size_t)(row0 + r) * C + k0 + c);
            xs[r][c + 0] = v4.x; xs[r][c + 1] = v4.y;
            xs[r][c + 2] = v4.z; xs[r][c + 3] = v4.w;
        }
        #pragma unroll
        for (int w = 0; w < 3; w++) {
            #pragma unroll
            for (int t = 0; t < 2; t++) {
                int f = tid * 2 + t;
                int r2 = f >> 4;
                int c2 = (f & 15) * 4;
                *reinterpret_cast<float4*>(&ws[w][r2][c2]) =
                    *reinterpret_cast<const float4*>(
                        Wm[w] + (size_t)(k0 + r2) * HS + c2);
            }
        }
        __syncthreads();

        #pragma unroll 8
        for (int kk = 0; kk < 32; kk++) {
            float a[4];
            #pragma unroll
            for (int i = 0; i < 4; i++) a[i] = xs[ty + 16 * i][kk];
            #pragma unroll
            for (int w = 0; w < 3; w++) {
                float4 b4 = *reinterpret_cast<float4*>(&ws[w][kk][tx * 4]);
                float bb[4] = {b4.x, b4.y, b4.z, b4.w};
                #pragma unroll
                for (int i = 0; i < 4; i++)
                    #pragma unroll
                    for (int j = 0; j < 4; j++)
                        acc[w][i][j] = fmaf(a[i], bb[j], acc[w][i][j]);
            }
        }
    }

    #pragma unroll
    for (int i = 0; i < 4; i++) {
        int r = row0 + ty + 16 * i;
        #pragma unroll
        for (int j = 0; j < 4; j++) {
            g_q[(size_t)r * HS + tx * 4 + j] = cvt_tf32(acc[0][i][j] * QSCALE);
            g_k[(size_t)r * HS + tx * 4 + j] = cvt_tf32(acc[1][i][j]);
        }
    }

    float* ts = &ws[0][0][0];
    __syncthreads();
    #pragma unroll
    for (int i = 0; i < 4; i++) {
        int rl = ty + 16 * i;
        #pragma unroll
        for (int j = 0; j < 4; j++)
            ts[rl * 65 + tx * 4 + j] = cvt_tf32(acc[2][i][j]);
    }
    __syncthreads();
    float* dst = g_vt + (size_t)row0 * HS;
    #pragma unroll
    for (int t = 0; t < 4; t++) {
        int f = tid + 256 * t;
        int kc = f & 15, dim = f >> 4;
        float4 w4;
        w4.x = ts[(4 * kc + 0) * 65 + dim];
        w4.y = ts[(4 * kc + 1) * 65 + dim];
        w4.z = ts[(4 * kc + 2) * 65 + dim];
        w4.w = ts[(4 * kc + 3) * 65 + dim];
        *reinterpret_cast<float4*>(dst + dim * 64 + kc * 4) = w4;
    }
}

// ---------------------------------------------------------------------------
// Flash attention — TWO independent 4-warp groups per 256-thread CTA.
// Group g (warps 4g..4g+3) processes q-tile 2*cta+g; groups have near-equal
// step counts (2c+1 vs 2c+2) so 8 warps stay resident on the critical CTA.
// Shift-free softmax needs no cross-group sync; each group has its own
// double-buffered K/VT smem region and named barrier (id 1+g).
// Per-q-row arithmetic identical to R9 (expect bit-identical output).
// ---------------------------------------------------------------------------
constexpr int KSTRIDE_B = 272;                 // bytes per smem row (68 floats)
constexpr int TILE_SM   = 64 * KSTRIDE_B;      // 17408 B
constexpr int GRP_SM    = 4 * TILE_SM;         // per-group: K0,K1,V0,V1
constexpr int SM_K0 = 0, SM_K1 = TILE_SM, SM_V0 = 2 * TILE_SM, SM_V1 = 3 * TILE_SM;
constexpr int FLASH_SMEM = 2 * GRP_SM;         // 139264 B

__global__ __launch_bounds__(256, 1) void flash_mma(float* __restrict__ out)
{
    extern __shared__ char sm[];
    const int tid  = threadIdx.x;
    const int grp  = tid >> 7;                  // 0 or 1
    const int gtid = tid & 127;                 // thread id within group
    const int wid  = gtid >> 5;                 // warp within group: 0..3
    const int lane = tid & 31;
    const int gid  = lane >> 2, qd = lane & 3;
    const int cta = blockIdx.x, b = blockIdx.y;

    const uint32_t smb =
        (uint32_t)__cvta_generic_to_shared(sm) + (uint32_t)grp * GRP_SM;
    const int barid = 1 + grp;

    const float* kb_base = g_k  + (size_t)b * T * HS;
    const float* vt_base = g_vt + (size_t)b * T * HS;

    const int qt = 2 * cta + grp;               // this group's q-tile
    const int nk = qt + 1;                      // causal key tiles

    const int lrow = ((lane >> 4) & 1) * 8 + (lane & 7);
    const int lofs = ((lane >> 3) & 1) * 16;

    auto prefetch = [&](int kb, int pbuf) {
        uint32_t dK = smb + (pbuf ? SM_K1 : SM_K0);
        uint32_t dV = smb + (pbuf ? SM_V1 : SM_V0);
        const float* sk = kb_base + (size_t)kb * 64 * HS;
        const float* sv = vt_base + (size_t)kb * 64 * HS;
        #pragma unroll
        for (int t = 0; t < 8; t++) {
            int f = gtid + 128 * t;             // 1024 chunks each
            int r = f >> 4, c = f & 15;
            cp16(dK + r * KSTRIDE_B + c * 16, sk + r * 64 + c * 4);
            cp16(dV + r * KSTRIDE_B + c * 16, sv + r * 64 + c * 4);
        }
        CP_COMMIT();
    };

    prefetch(0, 0);

    // Q fragments (tf32-rounded + scaled in proj)
    uint32_t qf[8][4];
    const float* qg = g_q + ((size_t)b * T + qt * 64 + 16 * wid) * HS;
    #pragma unroll
    for (int k = 0; k < 8; k++) {
        qf[k][0] = __float_as_uint(__ldg(qg + (gid    ) * 64 + k * 8 + qd    ));
        qf[k][1] = __float_as_uint(__ldg(qg + (gid + 8) * 64 + k * 8 + qd    ));
        qf[k][2] = __float_as_uint(__ldg(qg + (gid    ) * 64 + k * 8 + qd + 4));
        qf[k][3] = __float_as_uint(__ldg(qg + (gid + 8) * 64 + k * 8 + qd + 4));
    }

    float O[8][4];
    #pragma unroll
    for (int nt = 0; nt < 8; nt++)
        #pragma unroll
        for (int e = 0; e < 4; e++) O[nt][e] = 0.f;
    float l0 = 0.f, l1 = 0.f;

    const int rowg0 = qt * 64 + 16 * wid + gid;

    for (int kb = 0; kb < nk; kb++) {
        const int cur = kb & 1;

        // My group's cp.async done; group barrier publishes copies and
        // orders this group's previous-iteration reads before overwrite.
        CP_WAIT(0);
        bar_group(barid);

        if (kb + 1 < nk) prefetch(kb + 1, cur ^ 1);

        const uint32_t ksm = smb + (cur ? SM_K1 : SM_K0);
        const uint32_t vsm = smb + (cur ? SM_V1 : SM_V0);

        // ---- S = Q @ K^T ----
        float S[8][4];
        #pragma unroll
        for (int nt = 0; nt < 8; nt++)
            #pragma unroll
            for (int e = 0; e < 4; e++) S[nt][e] = 0.f;

        #pragma unroll
        for (int k = 0; k < 8; k++) {
            uint32_t bf[8][2];
            #pragma unroll
            for (int g = 0; g < 4; g++) {
                uint32_t addr = ksm + (16 * g + lrow) * KSTRIDE_B + lofs + k * 32;
                ldm4(bf[2*g][0], bf[2*g][1], bf[2*g+1][0], bf[2*g+1][1], addr);
            }
            #pragma unroll
            for (int nt = 0; nt < 8; nt++) mma8(S[nt], qf[k], bf[nt]);
        }

        // ---- softmax (shift-free) + tf32 rounding; l from rounded P ----
        const bool diag = (kb == qt);
        const int col0g = kb * 64;
        #pragma unroll
        for (int nt = 0; nt < 8; nt++) {
            float p0 = fast_exp2(S[nt][0]);
            float p1 = fast_exp2(S[nt][1]);
            float p2 = fast_exp2(S[nt][2]);
            float p3 = fast_exp2(S[nt][3]);
            if (diag) {
                int cb = col0g + 8 * nt + 2 * qd;
                if (cb     > rowg0)     p0 = 0.f;
                if (cb + 1 > rowg0)     p1 = 0.f;
                if (cb     > rowg0 + 8) p2 = 0.f;
                if (cb + 1 > rowg0 + 8) p3 = 0.f;
            }
            p0 = cvt_tf32(p0); p1 = cvt_tf32(p1);
            p2 = cvt_tf32(p2); p3 = cvt_tf32(p3);
            l0 += p0 + p1;
            l1 += p2 + p3;
            S[nt][0] = p0; S[nt][1] = p1; S[nt][2] = p2; S[nt][3] = p3;
        }

        // ---- P: D-frag -> A-frag permutation (in-warp) ----
        uint32_t pf[8][4];
        const int base = lane & ~3;
        const int s0 = base + (qd >> 1);
        const int s2 = s0 + 2;
        const bool odd = (qd & 1);
        #pragma unroll
        for (int nt = 0; nt < 8; nt++) {
            float x0 = __shfl_sync(0xffffffffu, S[nt][0], s0);
            float x1 = __shfl_sync(0xffffffffu, S[nt][1], s0);
            float y0 = __shfl_sync(0xffffffffu, S[nt][2], s0);
            float y1 = __shfl_sync(0xffffffffu, S[nt][3], s0);
            float x2 = __shfl_sync(0xffffffffu, S[nt][0], s2);
            float x3 = __shfl_sync(0xffffffffu, S[nt][1], s2);
            float y2 = __shfl_sync(0xffffffffu, S[nt][2], s2);
            float y3 = __shfl_sync(0xffffffffu, S[nt][3], s2);
            pf[nt][0] = __float_as_uint(odd ? x1 : x0);
            pf[nt][1] = __float_as_uint(odd ? y1 : y0);
            pf[nt][2] = __float_as_uint(odd ? x3 : x2);
            pf[nt][3] = __float_as_uint(odd ? y3 : y2);
        }

        // ---- O += P @ V (VT is dim-major) ----
        #pragma unroll
        for (int k = 0; k < 8; k++) {
            uint32_t bf[8][2];
            #pragma unroll
            for (int g = 0; g < 4; g++) {
                uint32_t addr = vsm + (16 * g + lrow) * KSTRIDE_B + lofs + k * 32;
                ldm4(bf[2*g][0], bf[2*g][1], bf[2*g+1][0], bf[2*g+1][1], addr);
            }
            #pragma unroll
            for (int nt = 0; nt < 8; nt++) mma8(O[nt], pf[k], bf[nt]);
        }
    }

    // ---- epilogue: reduce l over quad, normalize, store ----
    l0 += __shfl_xor_sync(0xffffffffu, l0, 1);
    l0 += __shfl_xor_sync(0xffffffffu, l0, 2);
    l1 += __shfl_xor_sync(0xffffffffu, l1, 1);
    l1 += __shfl_xor_sync(0xffffffffu, l1, 2);
    const float inv0 = 1.f / l0, inv1 = 1.f / l1;

    float* og = out + ((size_t)b * T + qt * 64 + 16 * wid) * HS;
    #pragma unroll
    for (int nt = 0; nt < 8; nt++) {
        int c0 = 8 * nt + 2 * qd;
        float2 lo = make_float2(O[nt][0] * inv0, O[nt][1] * inv0);
        float2 hi = make_float2(O[nt][2] * inv1, O[nt][3] * inv1);
        *reinterpret_cast<float2*>(og + (gid    ) * 64 + c0) = lo;
        *reinterpret_cast<float2*>(og + (gid + 8) * 64 + c0) = hi;
    }
}

// ---------------------------------------------------------------------------
extern "C" void kernel_launch(void* const* d_in, const int* in_sizes, int n_in,
                              void* d_out, int out_size)
{
    const float* x  = (const float*)d_in[0];
    const float* Wk = (const float*)d_in[1];
    const float* Wq = (const float*)d_in[2];
    const float* Wv = (const float*)d_in[3];
    float* out = (float*)d_out;

    cudaFuncSetAttribute(flash_mma,
                         cudaFuncAttributeMaxDynamicSharedMemorySize, FLASH_SMEM);

    proj_fused<<<(B * T) / 64, 256>>>(x, Wk, Wq, Wv);
    flash_mma<<<dim3(32, B), 256, FLASH_SMEM>>>(out);
}

// round 13
// speedup vs baseline: 1.4544x; 1.4544x over previous
#include <cuda_runtime.h>
#include <cstdint>

// Problem constants
constexpr int B  = 4;
constexpr int T  = 4096;
constexpr int C  = 512;
constexpr int HS = 64;
// Q pre-scale folded into projection: (1/sqrt(64)) * log2(e)
constexpr float QSCALE = 0.18033688011112042f;

// Scratch — __device__ globals, no allocation.
__device__ __align__(16) float g_q[B * T * HS];   // tf32-rounded, pre-scaled
__device__ __align__(16) float g_k[B * T * HS];   // tf32-rounded
__device__ __align__(16) float g_vt[B * T * HS];  // [b][tile][dim][key], tf32-rounded
__device__ __align__(16) float g_po[2][B * T * HS]; // partial O per key-parity half
__device__ __align__(16) float g_pl[2][B * T];      // partial l per key-parity half

// ---------------------------------------------------------------------------
// Helpers (sm_80-level PTX only — safe for compute_100 baseline target)
// ---------------------------------------------------------------------------
__device__ __forceinline__ float cvt_tf32(float x) {
    uint32_t y;                        // tf32 cvt destination must be .b32
    asm("cvt.rna.tf32.f32 %0, %1;" : "=r"(y) : "f"(x));
    return __uint_as_float(y);
}
__device__ __forceinline__ float fast_exp2(float x) {
    float y;
    asm("ex2.approx.f32 %0, %1;" : "=f"(y) : "f"(x));
    return y;
}
__device__ __forceinline__ void cp16(uint32_t dst, const void* src) {
    asm volatile("cp.async.cg.shared.global [%0], [%1], 16;" :: "r"(dst), "l"(src));
}
#define CP_COMMIT() asm volatile("cp.async.commit_group;" ::: "memory")
#define CP_WAIT(n)  asm volatile("cp.async.wait_group %0;" :: "n"(n) : "memory")

__device__ __forceinline__ void ldm4(uint32_t& r0, uint32_t& r1, uint32_t& r2,
                                     uint32_t& r3, uint32_t addr) {
    asm volatile("ldmatrix.sync.aligned.m8n8.x4.shared.b16 {%0,%1,%2,%3}, [%4];"
                 : "=r"(r0), "=r"(r1), "=r"(r2), "=r"(r3) : "r"(addr));
}
// D(16x8,f32) += A(16x8,tf32) * B(8x8,tf32)
__device__ __forceinline__ void mma8(float* d, const uint32_t* a, const uint32_t* b) {
    asm volatile(
        "mma.sync.aligned.m16n8k8.row.col.f32.tf32.tf32.f32 "
        "{%0,%1,%2,%3},{%4,%5,%6,%7},{%8,%9},{%0,%1,%2,%3};"
        : "+f"(d[0]), "+f"(d[1]), "+f"(d[2]), "+f"(d[3])
        : "r"(a[0]), "r"(a[1]), "r"(a[2]), "r"(a[3]), "r"(b[0]), "r"(b[1]));
}

// ---------------------------------------------------------------------------
// Fused projection — IDENTICAL to R9 (passing). One pass over x -> q, k, vt.
// ---------------------------------------------------------------------------
__global__ __launch_bounds__(256) void proj_fused(
    const float* __restrict__ x,
    const float* __restrict__ Wk,
    const float* __restrict__ Wq,
    const float* __restrict__ Wv)
{
    __shared__ float xs[64][33];        // 8.4 KB
    __shared__ float ws[3][32][64];     // 24 KB; reused as ts[64*65] in epilogue

    const int tid = threadIdx.x;
    const int tx = tid & 15, ty = tid >> 4;
    const int row0 = blockIdx.x * 64;

    const float* Wm[3] = {Wq, Wk, Wv};

    float acc[3][4][4] = {};

    for (int k0 = 0; k0 < C; k0 += 32) {
        __syncthreads();
        #pragma unroll
        for (int t = 0; t < 2; t++) {
            int f = tid * 2 + t;
            int r = f >> 3;
            int c = (f & 7) * 4;
            float4 v4 = *reinterpret_cast<const float4*>(
                x + (size_t)(row0 + r) * C + k0 + c);
            xs[r][c + 0] = v4.x; xs[r][c + 1] = v4.y;
            xs[r][c + 2] = v4.z; xs[r][c + 3] = v4.w;
        }
        #pragma unroll
        for (int w = 0; w < 3; w++) {
            #pragma unroll
            for (int t = 0; t < 2; t++) {
                int f = tid * 2 + t;
                int r2 = f >> 4;
                int c2 = (f & 15) * 4;
                *reinterpret_cast<float4*>(&ws[w][r2][c2]) =
                    *reinterpret_cast<const float4*>(
                        Wm[w] + (size_t)(k0 + r2) * HS + c2);
            }
        }
        __syncthreads();

        #pragma unroll 8
        for (int kk = 0; kk < 32; kk++) {
            float a[4];
            #pragma unroll
            for (int i = 0; i < 4; i++) a[i] = xs[ty + 16 * i][kk];
            #pragma unroll
            for (int w = 0; w < 3; w++) {
                float4 b4 = *reinterpret_cast<float4*>(&ws[w][kk][tx * 4]);
                float bb[4] = {b4.x, b4.y, b4.z, b4.w};
                #pragma unroll
                for (int i = 0; i < 4; i++)
                    #pragma unroll
                    for (int j = 0; j < 4; j++)
                        acc[w][i][j] = fmaf(a[i], bb[j], acc[w][i][j]);
            }
        }
    }

    #pragma unroll
    for (int i = 0; i < 4; i++) {
        int r = row0 + ty + 16 * i;
        #pragma unroll
        for (int j = 0; j < 4; j++) {
            g_q[(size_t)r * HS + tx * 4 + j] = cvt_tf32(acc[0][i][j] * QSCALE);
            g_k[(size_t)r * HS + tx * 4 + j] = cvt_tf32(acc[1][i][j]);
        }
    }

    float* ts = &ws[0][0][0];
    __syncthreads();
    #pragma unroll
    for (int i = 0; i < 4; i++) {
        int rl = ty + 16 * i;
        #pragma unroll
        for (int j = 0; j < 4; j++)
            ts[rl * 65 + tx * 4 + j] = cvt_tf32(acc[2][i][j]);
    }
    __syncthreads();
    float* dst = g_vt + (size_t)row0 * HS;
    #pragma unroll
    for (int t = 0; t < 4; t++) {
        int f = tid + 256 * t;
        int kc = f & 15, dim = f >> 4;
        float4 w4;
        w4.x = ts[(4 * kc + 0) * 65 + dim];
        w4.y = ts[(4 * kc + 1) * 65 + dim];
        w4.z = ts[(4 * kc + 2) * 65 + dim];
        w4.w = ts[(4 * kc + 3) * 65 + dim];
        *reinterpret_cast<float4*>(dst + dim * 64 + kc * 4) = w4;
    }
}

// ---------------------------------------------------------------------------
// Flash attention, balanced split-K by key-tile parity.
// grid (64, B), 128 threads. CTA (c = bx&31, half = bx>>5) processes q-tile
// pair {c, 63-c} but ONLY key tiles kb ≡ half (mod 2) -> 32-33 steps per CTA
// (balanced). Shift-free softmax => partials combine by pure addition:
// CTA writes unnormalized partial O and partial l; combine kernel finishes.
// Per-step arithmetic identical to R9. 2 CTAs/SM co-resident.
// ---------------------------------------------------------------------------
constexpr int KSTRIDE_B = 272;                 // bytes per smem row (68 floats)
constexpr int TILE_SM   = 64 * KSTRIDE_B;      // 17408 B
constexpr int SM_K0 = 0, SM_K1 = TILE_SM, SM_V0 = 2 * TILE_SM, SM_V1 = 3 * TILE_SM;
constexpr int FLASH_SMEM = 4 * TILE_SM;        // 69632 B

__global__ __launch_bounds__(128, 2) void flash_mma()
{
    extern __shared__ char sm[];
    const uint32_t smb = (uint32_t)__cvta_generic_to_shared(sm);
    const int tid = threadIdx.x;
    const int wid = tid >> 5, lane = tid & 31;
    const int gid = lane >> 2, qd = lane & 3;
    const int c = blockIdx.x & 31, half = blockIdx.x >> 5;
    const int b = blockIdx.y;

    const float* kb_base = g_k  + (size_t)b * T * HS;
    const float* vt_base = g_vt + (size_t)b * T * HS;

    const int qts[2] = {c, 63 - c};
    const int n0 = (qts[0] >= half) ? (qts[0] - half) / 2 + 1 : 0;
    const int n1 = (qts[1] >= half) ? (qts[1] - half) / 2 + 1 : 0;
    const int ntot = n0 + n1;

    const int lrow = ((lane >> 4) & 1) * 8 + (lane & 7);
    const int lofs = ((lane >> 3) & 1) * 16;

    auto kb_of = [&](int i) {
        return (i < n0) ? (half + 2 * i) : (half + 2 * (i - n0));
    };

    auto prefetch = [&](int kb, int pbuf) {
        uint32_t dK = smb + (pbuf ? SM_K1 : SM_K0);
        uint32_t dV = smb + (pbuf ? SM_V1 : SM_V0);
        const float* sk = kb_base + (size_t)kb * 64 * HS;
        const float* sv = vt_base + (size_t)kb * 64 * HS;
        #pragma unroll
        for (int t = 0; t < 8; t++) {
            int f = tid + 128 * t;              // 1024 chunks each
            int r = f >> 4, cc = f & 15;
            cp16(dK + r * KSTRIDE_B + cc * 16, sk + r * 64 + cc * 4);
            cp16(dV + r * KSTRIDE_B + cc * 16, sv + r * 64 + cc * 4);
        }
        CP_COMMIT();
    };

    prefetch(kb_of(0), 0);     // ntot >= 32 always

    int i = 0;                 // global step index (buffer parity)

    for (int ph = 0; ph < 2; ph++) {
        const int qt = qts[ph];
        const int n = ph ? n1 : n0;

        // Q fragments (tf32-rounded + scaled in proj)
        uint32_t qf[8][4];
        const float* qg = g_q + ((size_t)b * T + qt * 64 + 16 * wid) * HS;
        #pragma unroll
        for (int k = 0; k < 8; k++) {
            qf[k][0] = __float_as_uint(__ldg(qg + (gid    ) * 64 + k * 8 + qd    ));
            qf[k][1] = __float_as_uint(__ldg(qg + (gid + 8) * 64 + k * 8 + qd    ));
            qf[k][2] = __float_as_uint(__ldg(qg + (gid    ) * 64 + k * 8 + qd + 4));
            qf[k][3] = __float_as_uint(__ldg(qg + (gid + 8) * 64 + k * 8 + qd + 4));
        }

        float O[8][4];
        #pragma unroll
        for (int nt = 0; nt < 8; nt++)
            #pragma unroll
            for (int e = 0; e < 4; e++) O[nt][e] = 0.f;
        float l0 = 0.f, l1 = 0.f;

        const int rowg0 = qt * 64 + 16 * wid + gid;

        for (int j = 0; j < n; j++, i++) {
            const int kb = half + 2 * j;
            const int cur = i & 1;

            // My cp.async for buffer `cur` complete; barrier publishes all
            // threads' copies and orders prior reads of the other buffer.
            CP_WAIT(0);
            __syncthreads();

            if (i + 1 < ntot) prefetch(kb_of(i + 1), cur ^ 1);

            const uint32_t ksm = smb + (cur ? SM_K1 : SM_K0);
            const uint32_t vsm = smb + (cur ? SM_V1 : SM_V0);

            // ---- S = Q @ K^T ----
            float S[8][4];
            #pragma unroll
            for (int nt = 0; nt < 8; nt++)
                #pragma unroll
                for (int e = 0; e < 4; e++) S[nt][e] = 0.f;

            #pragma unroll
            for (int k = 0; k < 8; k++) {
                uint32_t bf[8][2];
                #pragma unroll
                for (int g = 0; g < 4; g++) {
                    uint32_t addr = ksm + (16 * g + lrow) * KSTRIDE_B + lofs + k * 32;
                    ldm4(bf[2*g][0], bf[2*g][1], bf[2*g+1][0], bf[2*g+1][1], addr);
                }
                #pragma unroll
                for (int nt = 0; nt < 8; nt++) mma8(S[nt], qf[k], bf[nt]);
            }

            // ---- softmax (shift-free) + tf32 rounding; l from rounded P ----
            const bool diag = (kb == qt);
            const int col0g = kb * 64;
            #pragma unroll
            for (int nt = 0; nt < 8; nt++) {
                float p0 = fast_exp2(S[nt][0]);
                float p1 = fast_exp2(S[nt][1]);
                float p2 = fast_exp2(S[nt][2]);
                float p3 = fast_exp2(S[nt][3]);
                if (diag) {
                    int cb = col0g + 8 * nt + 2 * qd;
                    if (cb     > rowg0)     p0 = 0.f;
                    if (cb + 1 > rowg0)     p1 = 0.f;
                    if (cb     > rowg0 + 8) p2 = 0.f;
                    if (cb + 1 > rowg0 + 8) p3 = 0.f;
                }
                p0 = cvt_tf32(p0); p1 = cvt_tf32(p1);
                p2 = cvt_tf32(p2); p3 = cvt_tf32(p3);
                l0 += p0 + p1;
                l1 += p2 + p3;
                S[nt][0] = p0; S[nt][1] = p1; S[nt][2] = p2; S[nt][3] = p3;
            }

            // ---- P: D-frag -> A-frag permutation (in-warp) ----
            uint32_t pf[8][4];
            const int base = lane & ~3;
            const int s0 = base + (qd >> 1);
            const int s2 = s0 + 2;
            const bool odd = (qd & 1);
            #pragma unroll
            for (int nt = 0; nt < 8; nt++) {
                float x0 = __shfl_sync(0xffffffffu, S[nt][0], s0);
                float x1 = __shfl_sync(0xffffffffu, S[nt][1], s0);
                float y0 = __shfl_sync(0xffffffffu, S[nt][2], s0);
                float y1 = __shfl_sync(0xffffffffu, S[nt][3], s0);
                float x2 = __shfl_sync(0xffffffffu, S[nt][0], s2);
                float x3 = __shfl_sync(0xffffffffu, S[nt][1], s2);
                float y2 = __shfl_sync(0xffffffffu, S[nt][2], s2);
                float y3 = __shfl_sync(0xffffffffu, S[nt][3], s2);
                pf[nt][0] = __float_as_uint(odd ? x1 : x0);
                pf[nt][1] = __float_as_uint(odd ? y1 : y0);
                pf[nt][2] = __float_as_uint(odd ? x3 : x2);
                pf[nt][3] = __float_as_uint(odd ? y3 : y2);
            }

            // ---- O += P @ V (VT is dim-major) ----
            #pragma unroll
            for (int k = 0; k < 8; k++) {
                uint32_t bf[8][2];
                #pragma unroll
                for (int g = 0; g < 4; g++) {
                    uint32_t addr = vsm + (16 * g + lrow) * KSTRIDE_B + lofs + k * 32;
                    ldm4(bf[2*g][0], bf[2*g][1], bf[2*g+1][0], bf[2*g+1][1], addr);
                }
                #pragma unroll
                for (int nt = 0; nt < 8; nt++) mma8(O[nt], pf[k], bf[nt]);
            }
        }

        // ---- epilogue: reduce l over quad, store UNNORMALIZED partials ----
        l0 += __shfl_xor_sync(0xffffffffu, l0, 1);
        l0 += __shfl_xor_sync(0xffffffffu, l0, 2);
        l1 += __shfl_xor_sync(0xffffffffu, l1, 1);
        l1 += __shfl_xor_sync(0xffffffffu, l1, 2);

        float* po = g_po[half] + ((size_t)b * T + qt * 64 + 16 * wid) * HS;
        #pragma unroll
        for (int nt = 0; nt < 8; nt++) {
            int c0 = 8 * nt + 2 * qd;
            *reinterpret_cast<float2*>(po + (gid    ) * 64 + c0) =
                make_float2(O[nt][0], O[nt][1]);
            *reinterpret_cast<float2*>(po + (gid + 8) * 64 + c0) =
                make_float2(O[nt][2], O[nt][3]);
        }
        if (qd == 0) {
            g_pl[half][(size_t)b * T + qt * 64 + 16 * wid + gid    ] = l0;
            g_pl[half][(size_t)b * T + qt * 64 + 16 * wid + gid + 8] = l1;
        }
    }
}

// ---------------------------------------------------------------------------
// Combine: out = (O0 + O1) / (l0 + l1).  1M float4 slots / 4 per thread.
// ---------------------------------------------------------------------------
__global__ __launch_bounds__(256) void combine_kernel(float* __restrict__ out)
{
    int idx = blockIdx.x * 256 + threadIdx.x;   // 0 .. B*T*HS/4 - 1
    int row = idx >> 4;                         // 16 float4 per row (HS=64)
    float inv = 1.f / (g_pl[0][row] + g_pl[1][row]);
    const float4 a = *reinterpret_cast<const float4*>(g_po[0] + (size_t)idx * 4);
    const float4 b = *reinterpret_cast<const float4*>(g_po[1] + (size_t)idx * 4);
    float4 r;
    r.x = (a.x + b.x) * inv;
    r.y = (a.y + b.y) * inv;
    r.z = (a.z + b.z) * inv;
    r.w = (a.w + b.w) * inv;
    *reinterpret_cast<float4*>(out + (size_t)idx * 4) = r;
}

// ---------------------------------------------------------------------------
extern "C" void kernel_launch(void* const* d_in, const int* in_sizes, int n_in,
                              void* d_out, int out_size)
{
    const float* x  = (const float*)d_in[0];
    const float* Wk = (const float*)d_in[1];
    const float* Wq = (const float*)d_in[2];
    const float* Wv = (const float*)d_in[3];
    float* out = (float*)d_out;

    cudaFuncSetAttribute(flash_mma,
                         cudaFuncAttributeMaxDynamicSharedMemorySize, FLASH_SMEM);

    proj_fused<<<(B * T) / 64, 256>>>(x, Wk, Wq, Wv);
    flash_mma<<<dim3(64, B), 128, FLASH_SMEM>>>();
    combine_kernel<<<(B * T * HS / 4) / 256, 256>>>(out);
}

// round 17
// speedup vs baseline: 2.0981x; 1.4426x over previous
#include <cuda_runtime.h>
#include <cstdint>

// Problem constants
constexpr int B  = 4;
constexpr int T  = 4096;
constexpr int C  = 512;
constexpr int HS = 64;
// Q pre-scale folded into projection: (1/sqrt(64)) * log2(e)
constexpr float QSCALE = 0.18033688011112042f;

// Scratch — __device__ globals, no allocation.
__device__ __align__(16) float g_q[B * T * HS];   // tf32-rounded, pre-scaled
__device__ __align__(16) float g_k[B * T * HS];   // tf32-rounded
__device__ __align__(16) float g_vt[B * T * HS];  // [b][tile][dim][key], tf32-rounded
__device__ __align__(16) float g_po[2][B * T * HS]; // partial O per key-parity half
__device__ __align__(16) float g_pl[2][B * T];      // partial l per key-parity half
__device__ __align__(16) float g_wt[3 * HS * C];    // W^T, tf32-rounded: rows 0-63 Wq^T,
                                                     // 64-127 Wk^T, 128-191 Wv^T

// ---------------------------------------------------------------------------
// Helpers (sm_80-level PTX only — safe for compute_100 baseline target)
// ---------------------------------------------------------------------------
__device__ __forceinline__ float cvt_tf32(float x) {
    uint32_t y;                        // tf32 cvt destination must be .b32
    asm("cvt.rna.tf32.f32 %0, %1;" : "=r"(y) : "f"(x));
    return __uint_as_float(y);
}
__device__ __forceinline__ float fast_exp2(float x) {
    float y;
    asm("ex2.approx.f32 %0, %1;" : "=f"(y) : "f"(x));
    return y;
}
__device__ __forceinline__ void cp16(uint32_t dst, const void* src) {
    asm volatile("cp.async.cg.shared.global [%0], [%1], 16;" :: "r"(dst), "l"(src));
}
#define CP_COMMIT() asm volatile("cp.async.commit_group;" ::: "memory")
#define CP_WAIT(n)  asm volatile("cp.async.wait_group %0;" :: "n"(n) : "memory")

__device__ __forceinline__ void ldm4(uint32_t& r0, uint32_t& r1, uint32_t& r2,
                                     uint32_t& r3, uint32_t addr) {
    asm volatile("ldmatrix.sync.aligned.m8n8.x4.shared.b16 {%0,%1,%2,%3}, [%4];"
                 : "=r"(r0), "=r"(r1), "=r"(r2), "=r"(r3) : "r"(addr));
}
// D(16x8,f32) += A(16x8,tf32) * B(8x8,tf32)
__device__ __forceinline__ void mma8(float* d, const uint32_t* a, const uint32_t* b) {
    asm volatile(
        "mma.sync.aligned.m16n8k8.row.col.f32.tf32.tf32.f32 "
        "{%0,%1,%2,%3},{%4,%5,%6,%7},{%8,%9},{%0,%1,%2,%3};"
        : "+f"(d[0]), "+f"(d[1]), "+f"(d[2]), "+f"(d[3])
        : "r"(a[0]), "r"(a[1]), "r"(a[2]), "r"(a[3]), "r"(b[0]), "r"(b[1]));
}

// ---------------------------------------------------------------------------
// wt_kernel: g_wt[64*m + n][c] = tf32(W_m[c][n])  (transpose + rna-round).
// grid (8, 3): blockIdx.x = 64-row k-tile, blockIdx.y = matrix (q,k,v).
// ---------------------------------------------------------------------------
__global__ __launch_bounds__(256) void wt_kernel(
    const float* __restrict__ Wk,
    const float* __restrict__ Wq,
    const float* __restrict__ Wv)
{
    __shared__ float ts[64 * 65];
    const int kt = blockIdx.x, m = blockIdx.y;
    const int tid = threadIdx.x;
    const float* W = (m == 0) ? Wq : (m == 1) ? Wk : Wv;

    #pragma unroll
    for (int t = 0; t < 4; t++) {
        int f = tid + 256 * t;                 // 1024 float4 chunks (64x64)
        int r = f >> 4, c4 = f & 15;
        float4 v = *reinterpret_cast<const float4*>(
            W + (size_t)(kt * 64 + r) * HS + c4 * 4);
        ts[r * 65 + c4 * 4 + 0] = v.x;
        ts[r * 65 + c4 * 4 + 1] = v.y;
        ts[r * 65 + c4 * 4 + 2] = v.z;
        ts[r * 65 + c4 * 4 + 3] = v.w;
    }
    __syncthreads();
    #pragma unroll
    for (int t = 0; t < 4; t++) {
        int f = tid + 256 * t;
        int n = f >> 4, c4 = f & 15;
        float4 w4;
        w4.x = cvt_tf32(ts[(4 * c4 + 0) * 65 + n]);
        w4.y = cvt_tf32(ts[(4 * c4 + 1) * 65 + n]);
        w4.z = cvt_tf32(ts[(4 * c4 + 2) * 65 + n]);
        w4.w = cvt_tf32(ts[(4 * c4 + 3) * 65 + n]);
        *reinterpret_cast<float4*>(
            g_wt + (size_t)(64 * m + n) * C + kt * 64 + c4 * 4) = w4;
    }
}

// ---------------------------------------------------------------------------
// proj_mma: tensor-core fused projection.
// 256 CTAs x 128 threads; CTA owns 64 x-rows, warp owns 16 rows x 192 outputs
// (24 n-tiles: 0-7 q, 8-15 k, 16-23 v). K-chunks of 32, double-buffered
// cp.async for x and wt; x rna-rounded in smem before use (tf32-exact A).
// A-frag from ldm4: r0=A[gid][qd], r1=A[gid][qd+4], r2=A[gid+8][qd],
// r3=A[gid+8][qd+4]  =>  af = {r0, r2, r1, r3}  (a1 is the +8-ROW element!)
// Epilogue: q,k direct stores; v staged through smem transpose -> g_vt.
// ---------------------------------------------------------------------------
constexpr int PSTR   = 144;                    // smem row stride (bytes)
constexpr int X_SZ   = 64 * PSTR;              // 9216 B
constexpr int WT_SZ  = 192 * PSTR;             // 27648 B
constexpr int BUF_SZ = X_SZ + WT_SZ;           // 36864 B
constexpr int PROJ_SMEM = 2 * BUF_SZ;          // 73728 B

__global__ __launch_bounds__(128) void proj_mma(const float* __restrict__ x)
{
    extern __shared__ char sm[];
    const uint32_t smb = (uint32_t)__cvta_generic_to_shared(sm);
    const int tid = threadIdx.x;
    const int wid = tid >> 5, lane = tid & 31;
    const int gid = lane >> 2, qd = lane & 3;
    const int row0 = blockIdx.x * 64;

    const int lrow = ((lane >> 4) & 1) * 8 + (lane & 7);
    const int lofs = ((lane >> 3) & 1) * 16;

    auto prefetch = [&](int kc, int buf) {
        uint32_t base = smb + (uint32_t)buf * BUF_SZ;
        #pragma unroll
        for (int t = 0; t < 4; t++) {          // x tile: 64 x 32 (512 f4)
            int f = tid + 128 * t;
            int r = f >> 3, c4 = f & 7;
            cp16(base + r * PSTR + c4 * 16,
                 x + (size_t)(row0 + r) * C + kc * 32 + c4 * 4);
        }
        #pragma unroll
        for (int t = 0; t < 12; t++) {         // wt tile: 192 x 32 (1536 f4)
            int f = tid + 128 * t;
            int r = f >> 3, c4 = f & 7;
            cp16(base + X_SZ + r * PSTR + c4 * 16,
                 g_wt + (size_t)r * C + kc * 32 + c4 * 4);
        }
        CP_COMMIT();
    };

    prefetch(0, 0);

    float acc[24][4];
    #pragma unroll
    for (int nt = 0; nt < 24; nt++)
        #pragma unroll
        for (int e = 0; e < 4; e++) acc[nt][e] = 0.f;

    for (int kc = 0; kc < 16; kc++) {
        const int cur = kc & 1;
        const uint32_t Xc  = smb + (uint32_t)cur * BUF_SZ;
        const uint32_t WTc = Xc + X_SZ;

        CP_WAIT(0);
        __syncthreads();

        // rna-round x tile in place (A operand must be tf32-exact)
        #pragma unroll
        for (int t = 0; t < 4; t++) {
            int f = tid + 128 * t;
            int r = f >> 3, c4 = f & 7;
            size_t off = (size_t)cur * BUF_SZ + r * PSTR + c4 * 16;
            float4 v = *reinterpret_cast<float4*>(sm + off);
            v.x = cvt_tf32(v.x); v.y = cvt_tf32(v.y);
            v.z = cvt_tf32(v.z); v.w = cvt_tf32(v.w);
            *reinterpret_cast<float4*>(sm + off) = v;
        }
        __syncthreads();

        if (kc + 1 < 16) prefetch(kc + 1, cur ^ 1);

        #pragma unroll
        for (int k = 0; k < 4; k++) {
            uint32_t af[4];
            // FIX (R15): a1 must be the +8-row element (r2), a2 the +4-col
            // element (r1): af = {r0, r2, r1, r3}.
            ldm4(af[0], af[2], af[1], af[3],
                 Xc + (16 * wid + lrow) * PSTR + lofs + k * 32);
            #pragma unroll
            for (int nt2 = 0; nt2 < 12; nt2++) {
                uint32_t b0[2], b1[2];
                ldm4(b0[0], b0[1], b1[0], b1[1],
                     WTc + (16 * nt2 + lrow) * PSTR + lofs + k * 32);
                mma8(acc[2 * nt2    ], af, b0);
                mma8(acc[2 * nt2 + 1], af, b1);
            }
        }
    }

    // ---- epilogue: q (nt 0-7), k (nt 8-15) direct float2 stores ----
    const int r0 = row0 + 16 * wid + gid;
    #pragma unroll
    for (int nt = 0; nt < 8; nt++) {
        int c0 = 8 * nt + 2 * qd;
        *reinterpret_cast<float2*>(g_q + (size_t)r0 * HS + c0) =
            make_float2(cvt_tf32(acc[nt][0] * QSCALE), cvt_tf32(acc[nt][1] * QSCALE));
        *reinterpret_cast<float2*>(g_q + (size_t)(r0 + 8) * HS + c0) =
            make_float2(cvt_tf32(acc[nt][2] * QSCALE), cvt_tf32(acc[nt][3] * QSCALE));
    }
    #pragma unroll
    for (int nt = 8; nt < 16; nt++) {
        int c0 = 8 * (nt - 8) + 2 * qd;
        *reinterpret_cast<float2*>(g_k + (size_t)r0 * HS + c0) =
            make_float2(cvt_tf32(acc[nt][0]), cvt_tf32(acc[nt][1]));
        *reinterpret_cast<float2*>(g_k + (size_t)(r0 + 8) * HS + c0) =
            make_float2(cvt_tf32(acc[nt][2]), cvt_tf32(acc[nt][3]));
    }

    // ---- v: stage through smem (buf0 region is dead), transpose to g_vt ----
    float* ts = reinterpret_cast<float*>(sm);   // 64*65 floats (16.6 KB)
    __syncthreads();
    const int rl0 = 16 * wid + gid;
    #pragma unroll
    for (int nt = 16; nt < 24; nt++) {
        int c0 = 8 * (nt - 16) + 2 * qd;
        ts[rl0 * 65 + c0]           = cvt_tf32(acc[nt][0]);
        ts[rl0 * 65 + c0 + 1]       = cvt_tf32(acc[nt][1]);
        ts[(rl0 + 8) * 65 + c0]     = cvt_tf32(acc[nt][2]);
        ts[(rl0 + 8) * 65 + c0 + 1] = cvt_tf32(acc[nt][3]);
    }
    __syncthreads();
    float* dst = g_vt + (size_t)row0 * HS;
    #pragma unroll
    for (int t = 0; t < 8; t++) {
        int f = tid + 128 * t;                  // 1024 float4 chunks
        int kc4 = f & 15, dim = f >> 4;
        float4 w4;
        w4.x = ts[(4 * kc4 + 0) * 65 + dim];
        w4.y = ts[(4 * kc4 + 1) * 65 + dim];
        w4.z = ts[(4 * kc4 + 2) * 65 + dim];
        w4.w = ts[(4 * kc4 + 3) * 65 + dim];
        *reinterpret_cast<float4*>(dst + dim * 64 + kc4 * 4) = w4;
    }
}

// ---------------------------------------------------------------------------
// Flash attention, balanced split-K by key-tile parity — IDENTICAL to R13.
// ---------------------------------------------------------------------------
constexpr int KSTRIDE_B = 272;                 // bytes per smem row (68 floats)
constexpr int TILE_SM   = 64 * KSTRIDE_B;      // 17408 B
constexpr int SM_K0 = 0, SM_K1 = TILE_SM, SM_V0 = 2 * TILE_SM, SM_V1 = 3 * TILE_SM;
constexpr int FLASH_SMEM = 4 * TILE_SM;        // 69632 B

__global__ __launch_bounds__(128, 2) void flash_mma()
{
    extern __shared__ char sm[];
    const uint32_t smb = (uint32_t)__cvta_generic_to_shared(sm);
    const int tid = threadIdx.x;
    const int wid = tid >> 5, lane = tid & 31;
    const int gid = lane >> 2, qd = lane & 3;
    const int c = blockIdx.x & 31, half = blockIdx.x >> 5;
    const int b = blockIdx.y;

    const float* kb_base = g_k  + (size_t)b * T * HS;
    const float* vt_base = g_vt + (size_t)b * T * HS;

    const int qts[2] = {c, 63 - c};
    const int n0 = (qts[0] >= half) ? (qts[0] - half) / 2 + 1 : 0;
    const int n1 = (qts[1] >= half) ? (qts[1] - half) / 2 + 1 : 0;
    const int ntot = n0 + n1;

    const int lrow = ((lane >> 4) & 1) * 8 + (lane & 7);
    const int lofs = ((lane >> 3) & 1) * 16;

    auto kb_of = [&](int i) {
        return (i < n0) ? (half + 2 * i) : (half + 2 * (i - n0));
    };

    auto prefetch = [&](int kb, int pbuf) {
        uint32_t dK = smb + (pbuf ? SM_K1 : SM_K0);
        uint32_t dV = smb + (pbuf ? SM_V1 : SM_V0);
        const float* sk = kb_base + (size_t)kb * 64 * HS;
        const float* sv = vt_base + (size_t)kb * 64 * HS;
        #pragma unroll
        for (int t = 0; t < 8; t++) {
            int f = tid + 128 * t;
            int r = f >> 4, cc = f & 15;
            cp16(dK + r * KSTRIDE_B + cc * 16, sk + r * 64 + cc * 4);
            cp16(dV + r * KSTRIDE_B + cc * 16, sv + r * 64 + cc * 4);
        }
        CP_COMMIT();
    };

    prefetch(kb_of(0), 0);

    int i = 0;

    for (int ph = 0; ph < 2; ph++) {
        const int qt = qts[ph];
        const int n = ph ? n1 : n0;

        uint32_t qf[8][4];
        const float* qg = g_q + ((size_t)b * T + qt * 64 + 16 * wid) * HS;
        #pragma unroll
        for (int k = 0; k < 8; k++) {
            qf[k][0] = __float_as_uint(__ldg(qg + (gid    ) * 64 + k * 8 + qd    ));
            qf[k][1] = __float_as_uint(__ldg(qg + (gid + 8) * 64 + k * 8 + qd    ));
            qf[k][2] = __float_as_uint(__ldg(qg + (gid    ) * 64 + k * 8 + qd + 4));
            qf[k][3] = __float_as_uint(__ldg(qg + (gid + 8) * 64 + k * 8 + qd + 4));
        }

        float O[8][4];
        #pragma unroll
        for (int nt = 0; nt < 8; nt++)
            #pragma unroll
            for (int e = 0; e < 4; e++) O[nt][e] = 0.f;
        float l0 = 0.f, l1 = 0.f;

        const int rowg0 = qt * 64 + 16 * wid + gid;

        for (int j = 0; j < n; j++, i++) {
            const int kb = half + 2 * j;
            const int cur = i & 1;

            CP_WAIT(0);
            __syncthreads();

            if (i + 1 < ntot) prefetch(kb_of(i + 1), cur ^ 1);

            const uint32_t ksm = smb + (cur ? SM_K1 : SM_K0);
            const uint32_t vsm = smb + (cur ? SM_V1 : SM_V0);

            float S[8][4];
            #pragma unroll
            for (int nt = 0; nt < 8; nt++)
                #pragma unroll
                for (int e = 0; e < 4; e++) S[nt][e] = 0.f;

            #pragma unroll
            for (int k = 0; k < 8; k++) {
                uint32_t bf[8][2];
                #pragma unroll
                for (int g = 0; g < 4; g++) {
                    uint32_t addr = ksm + (16 * g + lrow) * KSTRIDE_B + lofs + k * 32;
                    ldm4(bf[2*g][0], bf[2*g][1], bf[2*g+1][0], bf[2*g+1][1], addr);
                }
                #pragma unroll
                for (int nt = 0; nt < 8; nt++) mma8(S[nt], qf[k], bf[nt]);
            }

            const bool diag = (kb == qt);
            const int col0g = kb * 64;
            #pragma unroll
            for (int nt = 0; nt < 8; nt++) {
                float p0 = fast_exp2(S[nt][0]);
                float p1 = fast_exp2(S[nt][1]);
                float p2 = fast_exp2(S[nt][2]);
                float p3 = fast_exp2(S[nt][3]);
                if (diag) {
                    int cb = col0g + 8 * nt + 2 * qd;
                    if (cb     > rowg0)     p0 = 0.f;
                    if (cb + 1 > rowg0)     p1 = 0.f;
                    if (cb     > rowg0 + 8) p2 = 0.f;
                    if (cb + 1 > rowg0 + 8) p3 = 0.f;
                }
                p0 = cvt_tf32(p0); p1 = cvt_tf32(p1);
                p2 = cvt_tf32(p2); p3 = cvt_tf32(p3);
                l0 += p0 + p1;
                l1 += p2 + p3;
                S[nt][0] = p0; S[nt][1] = p1; S[nt][2] = p2; S[nt][3] = p3;
            }

            uint32_t pf[8][4];
            const int base = lane & ~3;
            const int s0 = base + (qd >> 1);
            const int s2 = s0 + 2;
            const bool odd = (qd & 1);
            #pragma unroll
            for (int nt = 0; nt < 8; nt++) {
                float x0 = __shfl_sync(0xffffffffu, S[nt][0], s0);
                float x1 = __shfl_sync(0xffffffffu, S[nt][1], s0);
                float y0 = __shfl_sync(0xffffffffu, S[nt][2], s0);
                float y1 = __shfl_sync(0xffffffffu, S[nt][3], s0);
                float x2 = __shfl_sync(0xffffffffu, S[nt][0], s2);
                float x3 = __shfl_sync(0xffffffffu, S[nt][1], s2);
                float y2 = __shfl_sync(0xffffffffu, S[nt][2], s2);
                float y3 = __shfl_sync(0xffffffffu, S[nt][3], s2);
                pf[nt][0] = __float_as_uint(odd ? x1 : x0);
                pf[nt][1] = __float_as_uint(odd ? y1 : y0);
                pf[nt][2] = __float_as_uint(odd ? x3 : x2);
                pf[nt][3] = __float_as_uint(odd ? y3 : y2);
            }

            #pragma unroll
            for (int k = 0; k < 8; k++) {
                uint32_t bf[8][2];
                #pragma unroll
                for (int g = 0; g < 4; g++) {
                    uint32_t addr = vsm + (16 * g + lrow) * KSTRIDE_B + lofs + k * 32;
                    ldm4(bf[2*g][0], bf[2*g][1], bf[2*g+1][0], bf[2*g+1][1], addr);
                }
                #pragma unroll
                for (int nt = 0; nt < 8; nt++) mma8(O[nt], pf[k], bf[nt]);
            }
        }

        l0 += __shfl_xor_sync(0xffffffffu, l0, 1);
        l0 += __shfl_xor_sync(0xffffffffu, l0, 2);
        l1 += __shfl_xor_sync(0xffffffffu, l1, 1);
        l1 += __shfl_xor_sync(0xffffffffu, l1, 2);

        float* po = g_po[half] + ((size_t)b * T + qt * 64 + 16 * wid) * HS;
        #pragma unroll
        for (int nt = 0; nt < 8; nt++) {
            int c0 = 8 * nt + 2 * qd;
            *reinterpret_cast<float2*>(po + (gid    ) * 64 + c0) =
                make_float2(O[nt][0], O[nt][1]);
            *reinterpret_cast<float2*>(po + (gid + 8) * 64 + c0) =
                make_float2(O[nt][2], O[nt][3]);
        }
        if (qd == 0) {
            g_pl[half][(size_t)b * T + qt * 64 + 16 * wid + gid    ] = l0;
            g_pl[half][(size_t)b * T + qt * 64 + 16 * wid + gid + 8] = l1;
        }
    }
}

// ---------------------------------------------------------------------------
// Combine: out = (O0 + O1) / (l0 + l1).
// ---------------------------------------------------------------------------
__global__ __launch_bounds__(256) void combine_kernel(float* __restrict__ out)
{
    int idx = blockIdx.x * 256 + threadIdx.x;
    int row = idx >> 4;
    float inv = 1.f / (g_pl[0][row] + g_pl[1][row]);
    const float4 a = *reinterpret_cast<const float4*>(g_po[0] + (size_t)idx * 4);
    const float4 b = *reinterpret_cast<const float4*>(g_po[1] + (size_t)idx * 4);
    float4 r;
    r.x = (a.x + b.x) * inv;
    r.y = (a.y + b.y) * inv;
    r.z = (a.z + b.z) * inv;
    r.w = (a.w + b.w) * inv;
    *reinterpret_cast<float4*>(out + (size_t)idx * 4) = r;
}

// ---------------------------------------------------------------------------
extern "C" void kernel_launch(void* const* d_in, const int* in_sizes, int n_in,
                              void* d_out, int out_size)
{
    const float* x  = (const float*)d_in[0];
    const float* Wk = (const float*)d_in[1];
    const float* Wq = (const float*)d_in[2];
    const float* Wv = (const float*)d_in[3];
    float* out = (float*)d_out;

    cudaFuncSetAttribute(flash_mma,
                         cudaFuncAttributeMaxDynamicSharedMemorySize, FLASH_SMEM);
    cudaFuncSetAttribute(proj_mma,
                         cudaFuncAttributeMaxDynamicSharedMemorySize, PROJ_SMEM);

    wt_kernel<<<dim3(8, 3), 256>>>(Wk, Wq, Wv);
    proj_mma<<<(B * T) / 64, 128, PROJ_SMEM>>>(x);
    flash_mma<<<dim3(64, B), 128, FLASH_SMEM>>>();
    combine_kernel<<<(B * T * HS / 4) / 256, 256>>>(out);
}